// round 5
// baseline (speedup 1.0000x reference)
#include <cuda_runtime.h>
#include <cuda_bf16.h>

// out = -0.1f * x over 67,108,864 fp32 elements (256 MiB in + 256 MiB out).
// Pure HBM stream. Persistent grid-stride over 32 KB tiles: grid sized to
// exactly fill the chip (148 SMs x 3 resident CTAs), eliminating the ~18
// wave transitions of the flat-grid version so the DRAM queue never drains.

#define ITEMS 4
#define THREADS 512
#define TILE (THREADS * ITEMS)   // float4s per tile = 2048 (32 KB)
#define PERSIST_BLOCKS 444       // 148 SMs * 3 CTAs/SM

// Persistent exact-fit: ntiles tiles, each fully covered (n4 % TILE == 0).
__global__ void __launch_bounds__(THREADS)
scale_kernel_persist(const float4* __restrict__ x,
                     float4* __restrict__ out,
                     int ntiles) {
    for (int t = blockIdx.x; t < ntiles; t += gridDim.x) {
        int base = t * TILE + threadIdx.x;

        float4 v[ITEMS];
        #pragma unroll
        for (int k = 0; k < ITEMS; k++) {
            v[k] = __ldcs(&x[base + k * THREADS]);
        }

        #pragma unroll
        for (int k = 0; k < ITEMS; k++) {
            float4 r;
            r.x = -0.1f * v[k].x;
            r.y = -0.1f * v[k].y;
            r.z = -0.1f * v[k].z;
            r.w = -0.1f * v[k].w;
            __stcs(&out[base + k * THREADS], r);
        }
    }
}

// Guarded generic kernel for sizes that don't divide into whole tiles.
__global__ void __launch_bounds__(THREADS)
scale_kernel_guarded(const float4* __restrict__ x,
                     float4* __restrict__ out,
                     int n4) {
    int base = blockIdx.x * TILE + threadIdx.x;
    #pragma unroll
    for (int k = 0; k < ITEMS; k++) {
        int i = base + k * THREADS;
        if (i < n4) {
            float4 v = __ldcs(&x[i]);
            float4 r;
            r.x = -0.1f * v.x;
            r.y = -0.1f * v.y;
            r.z = -0.1f * v.z;
            r.w = -0.1f * v.w;
            __stcs(&out[i], r);
        }
    }
}

// Scalar tail for element counts not divisible by 4.
__global__ void scale_kernel_tail(const float* __restrict__ x,
                                  float* __restrict__ out,
                                  int start, int n) {
    int i = start + blockIdx.x * blockDim.x + threadIdx.x;
    if (i < n) {
        out[i] = -0.1f * x[i];
    }
}

extern "C" void kernel_launch(void* const* d_in, const int* in_sizes, int n_in,
                              void* d_out, int out_size) {
    const float* x = (const float*)d_in[0];
    float* out = (float*)d_out;
    int n = in_sizes[0];

    int n4 = n / 4;
    if (n4 > 0) {
        if (n4 % TILE == 0) {
            int ntiles = n4 / TILE;
            int blocks = ntiles < PERSIST_BLOCKS ? ntiles : PERSIST_BLOCKS;
            scale_kernel_persist<<<blocks, THREADS>>>(
                (const float4*)x, (float4*)out, ntiles);
        } else {
            int blocks = (n4 + TILE - 1) / TILE;
            scale_kernel_guarded<<<blocks, THREADS>>>(
                (const float4*)x, (float4*)out, n4);
        }
    }
    int tail_start = n4 * 4;
    int tail = n - tail_start;
    if (tail > 0) {
        scale_kernel_tail<<<1, 256>>>(x, out, tail_start, n);
    }
}

// round 6
// speedup vs baseline: 1.1308x; 1.1308x over previous
#include <cuda_runtime.h>
#include <cuda_bf16.h>

// out = -0.1f * x over 67,108,864 fp32 elements (256 MiB in + 256 MiB out).
// Pure HBM stream. Flat exact-fit grid (persistent variant regressed: the
// grid-stride loop serializes tile bursts per warp). This round: ITEMS=2 x
// THREADS=512 — lowest register pressure / highest occupancy point on the
// sweep (1x256=79.2, 4x256=74.7, 4x512=74.0, 8x256=75.2 us).

#define ITEMS 2
#define THREADS 512
#define TILE (THREADS * ITEMS)

// Exact-fit: grid covers n4 exactly, no bounds checks.
__global__ void __launch_bounds__(THREADS)
scale_kernel_exact(const float4* __restrict__ x,
                   float4* __restrict__ out) {
    int base = blockIdx.x * TILE + threadIdx.x;

    float4 v[ITEMS];
    #pragma unroll
    for (int k = 0; k < ITEMS; k++) {
        v[k] = __ldcs(&x[base + k * THREADS]);
    }

    #pragma unroll
    for (int k = 0; k < ITEMS; k++) {
        float4 r;
        r.x = -0.1f * v[k].x;
        r.y = -0.1f * v[k].y;
        r.z = -0.1f * v[k].z;
        r.w = -0.1f * v[k].w;
        __stcs(&out[base + k * THREADS], r);
    }
}

// Guarded generic kernel for sizes that don't divide into whole tiles.
__global__ void __launch_bounds__(THREADS)
scale_kernel_guarded(const float4* __restrict__ x,
                     float4* __restrict__ out,
                     int n4) {
    int base = blockIdx.x * TILE + threadIdx.x;
    #pragma unroll
    for (int k = 0; k < ITEMS; k++) {
        int i = base + k * THREADS;
        if (i < n4) {
            float4 v = __ldcs(&x[i]);
            float4 r;
            r.x = -0.1f * v.x;
            r.y = -0.1f * v.y;
            r.z = -0.1f * v.z;
            r.w = -0.1f * v.w;
            __stcs(&out[i], r);
        }
    }
}

// Scalar tail for element counts not divisible by 4.
__global__ void scale_kernel_tail(const float* __restrict__ x,
                                  float* __restrict__ out,
                                  int start, int n) {
    int i = start + blockIdx.x * blockDim.x + threadIdx.x;
    if (i < n) {
        out[i] = -0.1f * x[i];
    }
}

extern "C" void kernel_launch(void* const* d_in, const int* in_sizes, int n_in,
                              void* d_out, int out_size) {
    const float* x = (const float*)d_in[0];
    float* out = (float*)d_out;
    int n = in_sizes[0];

    int n4 = n / 4;
    if (n4 > 0) {
        if (n4 % TILE == 0) {
            scale_kernel_exact<<<n4 / TILE, THREADS>>>(
                (const float4*)x, (float4*)out);
        } else {
            int blocks = (n4 + TILE - 1) / TILE;
            scale_kernel_guarded<<<blocks, THREADS>>>(
                (const float4*)x, (float4*)out, n4);
        }
    }
    int tail_start = n4 * 4;
    int tail = n - tail_start;
    if (tail > 0) {
        scale_kernel_tail<<<1, 256>>>(x, out, tail_start, n);
    }
}